// round 11
// baseline (speedup 1.0000x reference)
#include <cuda_runtime.h>
#include <cstdint>

#define N_ROWS 512
#define D_COLS 256
#define NBLK 128                  // one CTA per column pair
#define THREADS 512               // one row per thread -> 3 independent LDGs
#define SCALE_F 16777216.0f       // 2^24 fixed-point scale

// Single word of global state: bits 8..63 = fixed-point sum, bits 0..7 = count
// (128 arrivals < 256). Zeroed at module load; finisher resets each call.
__device__ unsigned long long gPacked;

#define SHFL2(v, s) do {                                   \
    (v).x += __shfl_xor_sync(0xFFFFFFFFu, (v).x, (s));     \
    (v).y += __shfl_xor_sync(0xFFFFFFFFu, (v).y, (s)); } while (0)

__global__ void __launch_bounds__(THREADS)
club_colsplit512(const float* __restrict__ mu,
                 const float* __restrict__ logvar,
                 const float* __restrict__ h,
                 float* __restrict__ out) {
    const int tid  = threadIdx.x;               // row 0..511
    const int lane = tid & 31;
    const int w    = tid >> 5;                  // warp 0..15
    const int g    = blockIdx.x;                // column pair: cols 2g, 2g+1

    const float2* __restrict__ h2 = (const float2*)h;
    const float2* __restrict__ m2 = (const float2*)mu;
    const float2* __restrict__ l2 = (const float2*)logvar;

    // ---- Phase 1: ONE row per thread; 3 independent float2 loads ----
    const int i2 = tid * (D_COLS / 2) + g;
    const float2 hv = h2[i2];
    const float2 mv = m2[i2];
    const float2 lv = l2[i2];

    float2 s1, s2, a, b, c;
#define ACC_C(C) {                                          \
        const float iv = __expf(-lv.C);                     \
        s1.C = hv.C;                                        \
        s2.C = hv.C * hv.C;                                 \
        a.C  = iv * mv.C;                                   \
        b.C  = iv;                                          \
        c.C  = iv * hv.C * (hv.C - 2.0f * mv.C); }
    ACC_C(x); ACC_C(y);
#undef ACC_C

    // ---- Phase 2: full-warp xor reduction (all lanes same 2 columns) ----
#pragma unroll
    for (int s = 16; s > 0; s >>= 1) {
        SHFL2(s1, s); SHFL2(s2, s); SHFL2(a, s); SHFL2(b, s); SHFL2(c, s);
    }

    // ---- Phase 3: 16 warps publish; warp 0 folds and finishes ----
    __shared__ float2 part[16][5];
    if (lane == 0) {
        part[w][0] = s1; part[w][1] = s2; part[w][2] = a;
        part[w][3] = b;  part[w][4] = c;
    }
    __syncthreads();
    if (w != 0) return;

    // Lanes 0..15 each take one warp's stats; xor 1,2,4,8 folds 16 -> 1.
    float2 S1 = {0,0}, S2 = {0,0}, A = {0,0}, B = {0,0}, C = {0,0};
    if (lane < 16) {
        S1 = part[lane][0]; S2 = part[lane][1]; A = part[lane][2];
        B  = part[lane][3]; C  = part[lane][4];
    }
#pragma unroll
    for (int s = 1; s <= 8; s <<= 1) {
        SHFL2(S1, s); SHFL2(S2, s); SHFL2(A, s); SHFL2(B, s); SHFL2(C, s);
    }

    if (lane == 0) {
        const float invN = 1.0f / (float)N_ROWS;
        const float term =
            (C.x + invN * (2.0f * S1.x * A.x - S2.x * B.x)) +
            (C.y + invN * (2.0f * S1.y * A.y - S2.y * B.y));

        // ONE packed atomic: value (bits 8..63) + arrival count (bits 0..7).
        // The 128th arriver holds the complete sum in old+myv.
        const long long fix = __float2ll_rn(term * SCALE_F);
        const unsigned long long myv = ((unsigned long long)fix << 8) + 1ull;
        const unsigned long long old = atomicAdd(&gPacked, myv);
        if ((old & 255ull) == (unsigned long long)(NBLK - 1)) {
            const long long tot = (long long)(old + myv);   // 256*F + 128
            const long long F   = tot >> 8;                 // exact
            out[0]  = (float)((-0.5 / (double)N_ROWS) *
                              ((double)F * (1.0 / (double)SCALE_F)));
            gPacked = 0ull;                                 // reset for replay
        }
    }
}

extern "C" void kernel_launch(void* const* d_in, const int* in_sizes, int n_in,
                              void* d_out, int out_size) {
    const float* mu     = (const float*)d_in[0];
    const float* logvar = (const float*)d_in[1];
    const float* h      = (const float*)d_in[2];
    float* out          = (float*)d_out;
    club_colsplit512<<<NBLK, THREADS>>>(mu, logvar, h, out);
}

// round 12
// speedup vs baseline: 1.2383x; 1.2383x over previous
#include <cuda_runtime.h>
#include <cstdint>

#define N_ROWS 512
#define D_COLS 256
#define NBLK 128                  // one CTA per column pair (cols 2g, 2g+1)
#define THREADS 128               // 4 warps; 4 rows per thread -> 12 indep LDGs
#define ROWS_PER_THREAD 4
#define SCALE_F 16777216.0f       // 2^24 fixed-point scale

// Single word of global state: bits 8..63 = fixed-point sum, bits 0..7 = count
// (128 arrivals < 256). Zeroed at module load; finisher resets each call.
__device__ unsigned long long gPacked;

#define SHFL2(v, s) do {                                   \
    (v).x += __shfl_xor_sync(0xFFFFFFFFu, (v).x, (s));     \
    (v).y += __shfl_xor_sync(0xFFFFFFFFu, (v).y, (s)); } while (0)

__global__ void __launch_bounds__(THREADS)
club_ilp4(const float* __restrict__ mu,
          const float* __restrict__ logvar,
          const float* __restrict__ h,
          float* __restrict__ out) {
    const int tid  = threadIdx.x;
    const int lane = tid & 31;
    const int w    = tid >> 5;                  // warp 0..3
    const int g    = blockIdx.x;                // column pair

    const float2* __restrict__ h2 = (const float2*)h;
    const float2* __restrict__ m2 = (const float2*)mu;
    const float2* __restrict__ l2 = (const float2*)logvar;

    // ---- Phase 1: 4 rows per thread, 12 independent float2 loads ----
    float2 hv[ROWS_PER_THREAD], mv[ROWS_PER_THREAD], lv[ROWS_PER_THREAD];
#pragma unroll
    for (int p = 0; p < ROWS_PER_THREAD; ++p) {
        const int row = tid + p * THREADS;      // 0..511
        const int i2  = row * (D_COLS / 2) + g;
        hv[p] = h2[i2];
        mv[p] = m2[i2];
        lv[p] = l2[i2];
    }

    float2 s1 = {0,0}, s2 = {0,0}, a = {0,0}, b = {0,0}, c = {0,0};
#define ACC_C(p, C) {                                       \
        const float iv = __expf(-lv[p].C);                  \
        s1.C += hv[p].C;                                    \
        s2.C += hv[p].C * hv[p].C;                          \
        a.C  += iv * mv[p].C;                               \
        b.C  += iv;                                         \
        c.C  += iv * hv[p].C * (hv[p].C - 2.0f * mv[p].C); }
#pragma unroll
    for (int p = 0; p < ROWS_PER_THREAD; ++p) { ACC_C(p, x); ACC_C(p, y); }
#undef ACC_C

    // ---- Phase 2: full-warp xor reduction (all lanes same 2 columns) ----
#pragma unroll
    for (int s = 16; s > 0; s >>= 1) {
        SHFL2(s1, s); SHFL2(s2, s); SHFL2(a, s); SHFL2(b, s); SHFL2(c, s);
    }

    // ---- Phase 3: 4 warps publish; warp 0 folds 4 entries and finishes ----
    __shared__ float2 part[4][5];
    if (lane == 0) {
        part[w][0] = s1; part[w][1] = s2; part[w][2] = a;
        part[w][3] = b;  part[w][4] = c;
    }
    __syncthreads();
    if (w != 0) return;

    float2 S1 = {0,0}, S2 = {0,0}, A = {0,0}, B = {0,0}, C = {0,0};
    if (lane < 4) {
        S1 = part[lane][0]; S2 = part[lane][1]; A = part[lane][2];
        B  = part[lane][3]; C  = part[lane][4];
    }
#pragma unroll
    for (int s = 1; s <= 2; s <<= 1) {
        SHFL2(S1, s); SHFL2(S2, s); SHFL2(A, s); SHFL2(B, s); SHFL2(C, s);
    }

    if (lane == 0) {
        const float invN = 1.0f / (float)N_ROWS;
        const float term =
            (C.x + invN * (2.0f * S1.x * A.x - S2.x * B.x)) +
            (C.y + invN * (2.0f * S1.y * A.y - S2.y * B.y));

        // ONE packed atomic: value (bits 8..63) + arrival count (bits 0..7).
        // The 128th arriver holds the complete sum in old+myv.
        const long long fix = __float2ll_rn(term * SCALE_F);
        const unsigned long long myv = ((unsigned long long)fix << 8) + 1ull;
        const unsigned long long old = atomicAdd(&gPacked, myv);
        if ((old & 255ull) == (unsigned long long)(NBLK - 1)) {
            const long long tot = (long long)(old + myv);   // 256*F + 128
            const long long F   = tot >> 8;                 // exact
            out[0]  = (float)((-0.5 / (double)N_ROWS) *
                              ((double)F * (1.0 / (double)SCALE_F)));
            gPacked = 0ull;                                 // reset for replay
        }
    }
}

extern "C" void kernel_launch(void* const* d_in, const int* in_sizes, int n_in,
                              void* d_out, int out_size) {
    const float* mu     = (const float*)d_in[0];
    const float* logvar = (const float*)d_in[1];
    const float* h      = (const float*)d_in[2];
    float* out          = (float*)d_out;
    club_ilp4<<<NBLK, THREADS>>>(mu, logvar, h, out);
}

// round 13
// speedup vs baseline: 1.2740x; 1.0288x over previous
#include <cuda_runtime.h>
#include <cstdint>

#define N_ROWS 512
#define D_COLS 256
#define NBLK 128                  // one CTA per column pair (cols 2g, 2g+1)
#define THREADS 256               // 8 warps; 2 rows/thread -> 6 indep LDGs
#define SCALE_F 16777216.0f       // 2^24 fixed-point scale

// Single word of global state: bits 8..63 = fixed-point sum, bits 0..7 = count
// (128 arrivals < 256). Zeroed at module load; finisher resets each call.
__device__ unsigned long long gPacked;

#define SHFL2(v, s) do {                                   \
    (v).x += __shfl_xor_sync(0xFFFFFFFFu, (v).x, (s));     \
    (v).y += __shfl_xor_sync(0xFFFFFFFFu, (v).y, (s)); } while (0)
#define SHFL1(v, s) (v) += __shfl_xor_sync(0xFFFFFFFFu, (v), (s))

__global__ void __launch_bounds__(THREADS)
club_best(const float* __restrict__ mu,
          const float* __restrict__ logvar,
          const float* __restrict__ h,
          float* __restrict__ out) {
    const int tid  = threadIdx.x;
    const int lane = tid & 31;
    const int w    = tid >> 5;                  // warp 0..7
    const int g    = blockIdx.x;                // column pair: cols 2g, 2g+1

    const float2* __restrict__ h2 = (const float2*)h;
    const float2* __restrict__ m2 = (const float2*)mu;
    const float2* __restrict__ l2 = (const float2*)logvar;

    // ---- Phase 1: 2 rows per thread; 6 independent float2 loads ----
    float2 s1 = {0,0}, s2 = {0,0}, a = {0,0}, b = {0,0};
    float  c  = 0.f;                            // C is linear in the final
                                                // term -> scalar fold now

#define ACC_C(C) {                                          \
        const float iv = __expf(-lv.C);                     \
        s1.C += hv.C;                                       \
        s2.C += hv.C * hv.C;                                \
        a.C  += iv * mv.C;                                  \
        b.C  += iv;                                         \
        c    += iv * hv.C * (hv.C - 2.0f * mv.C); }

#pragma unroll
    for (int p = 0; p < 2; ++p) {
        const int row = tid + p * THREADS;      // 0..511
        const int i2  = row * (D_COLS / 2) + g;
        const float2 hv = h2[i2];
        const float2 mv = m2[i2];
        const float2 lv = l2[i2];
        ACC_C(x); ACC_C(y);
    }
#undef ACC_C

    // ---- Phase 2: full-warp xor reduction (9 floats instead of 10) ----
#pragma unroll
    for (int s = 16; s > 0; s >>= 1) {
        SHFL2(s1, s); SHFL2(s2, s); SHFL2(a, s); SHFL2(b, s); SHFL1(c, s);
    }

    // ---- Phase 3: 8 warps publish; warp 0 folds 8 entries and finishes ----
    __shared__ float2 part[8][4];
    __shared__ float  partc[8];
    if (lane == 0) {
        part[w][0] = s1; part[w][1] = s2; part[w][2] = a; part[w][3] = b;
        partc[w]   = c;
    }
    __syncthreads();
    if (w != 0) return;

    float2 S1 = {0,0}, S2 = {0,0}, A = {0,0}, B = {0,0};
    float  Cs = 0.f;
    if (lane < 8) {
        S1 = part[lane][0]; S2 = part[lane][1];
        A  = part[lane][2]; B  = part[lane][3];
        Cs = partc[lane];
    }
#pragma unroll
    for (int s = 1; s <= 4; s <<= 1) {
        SHFL2(S1, s); SHFL2(S2, s); SHFL2(A, s); SHFL2(B, s); SHFL1(Cs, s);
    }

    if (lane == 0) {
        const float invN = 1.0f / (float)N_ROWS;
        const float term = Cs +
            invN * (2.0f * (S1.x * A.x + S1.y * A.y)
                         - (S2.x * B.x + S2.y * B.y));

        // ONE packed atomic: value (bits 8..63) + arrival count (bits 0..7).
        // The 128th arriver holds the complete sum in old+myv.
        const long long fix = __float2ll_rn(term * SCALE_F);
        const unsigned long long myv = ((unsigned long long)fix << 8) + 1ull;
        const unsigned long long old = atomicAdd(&gPacked, myv);
        if ((old & 255ull) == (unsigned long long)(NBLK - 1)) {
            const long long tot = (long long)(old + myv);   // 256*F + 128
            const long long F   = tot >> 8;                 // exact
            out[0]  = (float)((-0.5 / (double)N_ROWS) *
                              ((double)F * (1.0 / (double)SCALE_F)));
            gPacked = 0ull;                                 // reset for replay
        }
    }
}

extern "C" void kernel_launch(void* const* d_in, const int* in_sizes, int n_in,
                              void* d_out, int out_size) {
    const float* mu     = (const float*)d_in[0];
    const float* logvar = (const float*)d_in[1];
    const float* h      = (const float*)d_in[2];
    float* out          = (float*)d_out;
    club_best<<<NBLK, THREADS>>>(mu, logvar, h, out);
}